// round 1
// baseline (speedup 1.0000x reference)
#include <cuda_runtime.h>
#include <cstdint>

using ull = unsigned long long;

// Problem constants (fixed by the dataset)
constexpr int ND   = 30000;   // dst nodes (== src nodes)
constexpr int D    = 256;     // channels
constexpr int R    = 8;       // relations
constexpr int KW   = R * D;   // 2048  (einsum K)
constexpr int KTOT = KW + D;  // 2304  (einsum K + root K)

// Scratch (device globals — no allocations allowed)
__device__ float g_sum[(size_t)ND * R * D];   // per-(dst,rel) feature sums, 245.76 MB
__device__ float g_cnt[ND * R];               // per-(dst,rel) edge counts
__device__ float g_h[(size_t)ND * D];         // layer-1 activations

// ---------------------------------------------------------------------------
// packed f32x2 helpers (FFMA2 is full-rate on sm_103a; 3-reg FFMA is half-rate)
// ---------------------------------------------------------------------------
__device__ __forceinline__ void fma2(ull& acc, ull a, ull b) {
    asm("fma.rn.f32x2 %0, %1, %2, %3;" : "=l"(acc) : "l"(a), "l"(b), "l"(acc));
}
__device__ __forceinline__ ull pack2(float x, float y) {
    ull r; asm("mov.b64 %0, {%1, %2};" : "=l"(r) : "f"(x), "f"(y)); return r;
}
__device__ __forceinline__ float2 unpack2(ull v) {
    float2 f; asm("mov.b64 {%0, %1}, %2;" : "=f"(f.x), "=f"(f.y) : "l"(v)); return f;
}

// ---------------------------------------------------------------------------
// Kernel 1: zero the sums + counts
// ---------------------------------------------------------------------------
__global__ void zero_kernel() {
    size_t stride = (size_t)gridDim.x * blockDim.x;
    size_t i = (size_t)blockIdx.x * blockDim.x + threadIdx.x;
    float4 z = make_float4(0.f, 0.f, 0.f, 0.f);
    size_t nsum4 = (size_t)ND * R * D / 4;
    for (size_t j = i; j < nsum4; j += stride) ((float4*)g_sum)[j] = z;
    size_t ncnt4 = (size_t)ND * R / 4;
    for (size_t j = i; j < ncnt4; j += stride) ((float4*)g_cnt)[j] = z;
}

// ---------------------------------------------------------------------------
// Kernel 2: scatter-add edges (one warp per edge).
// Index dtype (int32 vs int64) detected at runtime: for int64 little-endian
// storage of values < 2^31, every odd int32 slot is 0.
// ---------------------------------------------------------------------------
__global__ void scatter_kernel(const float* __restrict__ x_src,
                               const void*  __restrict__ ei,
                               const void*  __restrict__ et,
                               int E) {
    int gw   = (blockIdx.x * blockDim.x + threadIdx.x) >> 5;
    int lane = threadIdx.x & 31;
    if (gw >= E) return;

    const int* ei32 = (const int*)ei;
    bool is64 = ((ei32[1] | ei32[3] | ei32[5] | ei32[7]) == 0);

    long long s, d, r;
    if (is64) {
        const long long* p = (const long long*)ei;
        s = p[gw]; d = p[E + gw]; r = ((const long long*)et)[gw];
    } else {
        s = ei32[gw]; d = ei32[E + gw]; r = ((const int*)et)[gw];
    }

    const float* xr  = x_src + (size_t)s * D;
    float*       out = g_sum + ((size_t)d * R + r) * D;
#pragma unroll
    for (int it = 0; it < D / 32; it++)
        atomicAdd(out + lane + 32 * it, xr[lane + 32 * it]);
    if (lane == 0) atomicAdd(&g_cnt[d * R + r], 1.0f);
}

// ---------------------------------------------------------------------------
// Kernel 3: fused GEMM  C = [agg_scaled | A_root] @ [W ; Wroot] + bias (+relu)
//   A logical shape (ND, 2304); K in [0,2048) reads g_sum scaled by 1/cnt,
//   K in [2048,2304) reads A_root (x_dst for layer 1, g_h for layer 2).
// Tile: 128x128x16, 256 threads, 8x8 microtile via 8 x (4 x f32x2) FFMA2.
// ---------------------------------------------------------------------------
constexpr int BM = 128, BN = 128, BK = 16;

__global__ __launch_bounds__(256)
void gemm_kernel(const float* __restrict__ Aroot_ext,
                 const float* __restrict__ W,      // (2048, 256) row-major
                 const float* __restrict__ Wroot,  // (256, 256) row-major
                 const float* __restrict__ bias,   // (256,)
                 float* __restrict__ Cout_ext,
                 int rootFromH, int writeH, int doRelu) {
    __shared__ __align__(16) float As[BM][BK];
    __shared__ __align__(16) float Bs[BK][BN];
    __shared__ float s_inv[BM * R];

    const float* Aroot = rootFromH ? g_h : Aroot_ext;
    float*       C     = writeH   ? g_h : Cout_ext;

    int tid  = threadIdx.x;
    int row0 = blockIdx.x * BM;
    int bn   = blockIdx.y;
    int tr   = tid >> 4;      // 0..15
    int tc   = tid & 15;      // 0..15

    // per-(row, relation) 1/max(cnt,1)
    for (int i = tid; i < BM * R; i += 256) {
        int rl = i >> 3, rr = i & 7;
        int grow = row0 + rl;
        float c = (grow < ND) ? g_cnt[grow * R + rr] : 1.0f;
        s_inv[i] = 1.0f / fmaxf(c, 1.0f);
    }
    __syncthreads();

    ull acc[8][4];
#pragma unroll
    for (int i = 0; i < 8; i++)
#pragma unroll
        for (int j = 0; j < 4; j++) acc[i][j] = 0ull;

    for (int k0 = 0; k0 < KTOT; k0 += BK) {
        // ---- load A tile (128 x 16), scale by 1/cnt in flight ----
#pragma unroll
        for (int l = 0; l < 2; l++) {
            int f  = tid + l * 256;          // 0..511 float4s
            int rl = f >> 2;
            int c4 = (f & 3) << 2;
            int grow = row0 + rl;
            float4 v = make_float4(0.f, 0.f, 0.f, 0.f);
            float sc = 0.f;
            if (grow < ND) {
                if (k0 < KW) {
                    v  = *(const float4*)(g_sum + (size_t)grow * KW + k0 + c4);
                    sc = s_inv[rl * R + (k0 >> 8)];
                } else {
                    v  = *(const float4*)(Aroot + (size_t)grow * D + (k0 - KW) + c4);
                    sc = 1.0f;
                }
            }
            float4 w = make_float4(v.x * sc, v.y * sc, v.z * sc, v.w * sc);
            *(float4*)&As[rl][c4] = w;
        }
        // ---- load B tile (16 x 128) ----
        const float* Bsrc = (k0 < KW) ? (W + (size_t)k0 * D)
                                      : (Wroot + (size_t)(k0 - KW) * D);
#pragma unroll
        for (int l = 0; l < 2; l++) {
            int f  = tid + l * 256;
            int kr = f >> 5;
            int c4 = (f & 31) << 2;
            float4 v = *(const float4*)(Bsrc + (size_t)kr * D + bn * BN + c4);
            *(float4*)&Bs[kr][c4] = v;
        }
        __syncthreads();

        // ---- microkernel ----
#pragma unroll
        for (int kk = 0; kk < BK; kk++) {
            float a[8];
#pragma unroll
            for (int i = 0; i < 8; i++) a[i] = As[tr * 8 + i][kk];
            ulonglong2 b0 = *(const ulonglong2*)&Bs[kk][tc * 4];
            ulonglong2 b1 = *(const ulonglong2*)&Bs[kk][64 + tc * 4];
            ull bb[4] = {b0.x, b0.y, b1.x, b1.y};
#pragma unroll
            for (int i = 0; i < 8; i++) {
                ull ad = pack2(a[i], a[i]);
#pragma unroll
                for (int j = 0; j < 4; j++) fma2(acc[i][j], ad, bb[j]);
            }
        }
        __syncthreads();
    }

    // ---- epilogue: bias (+relu), store ----
    int cb = bn * BN + tc * 4;
    float4 bsa = *(const float4*)&bias[cb];
    float4 bsb = *(const float4*)&bias[cb + 64];
#pragma unroll
    for (int i = 0; i < 8; i++) {
        int grow = row0 + tr * 8 + i;
        if (grow >= ND) continue;
        float2 p0 = unpack2(acc[i][0]), p1 = unpack2(acc[i][1]);
        float2 p2 = unpack2(acc[i][2]), p3 = unpack2(acc[i][3]);
        float4 o0 = make_float4(p0.x + bsa.x, p0.y + bsa.y, p1.x + bsa.z, p1.y + bsa.w);
        float4 o1 = make_float4(p2.x + bsb.x, p2.y + bsb.y, p3.x + bsb.z, p3.y + bsb.w);
        if (doRelu) {
            o0.x = fmaxf(o0.x, 0.f); o0.y = fmaxf(o0.y, 0.f);
            o0.z = fmaxf(o0.z, 0.f); o0.w = fmaxf(o0.w, 0.f);
            o1.x = fmaxf(o1.x, 0.f); o1.y = fmaxf(o1.y, 0.f);
            o1.z = fmaxf(o1.z, 0.f); o1.w = fmaxf(o1.w, 0.f);
        }
        float* Crow = C + (size_t)grow * D;
        *(float4*)&Crow[cb]      = o0;
        *(float4*)&Crow[cb + 64] = o1;
    }
}

// ---------------------------------------------------------------------------
extern "C" void kernel_launch(void* const* d_in, const int* in_sizes, int n_in,
                              void* d_out, int out_size) {
    const float* x_src = (const float*)d_in[0];
    const float* x_dst = (const float*)d_in[1];
    const void*  ei    = d_in[2];
    const void*  et    = d_in[3];
    const float* w1    = (const float*)d_in[4];
    const float* root1 = (const float*)d_in[5];
    const float* b1    = (const float*)d_in[6];
    const float* w2    = (const float*)d_in[7];
    const float* root2 = (const float*)d_in[8];
    const float* b2    = (const float*)d_in[9];
    float* out = (float*)d_out;
    int E = in_sizes[3];   // edge_type element count

    zero_kernel<<<2368, 256>>>();

    int warps_per_blk = 256 / 32;
    int nblk = (E + warps_per_blk - 1) / warps_per_blk;
    scatter_kernel<<<nblk, 256>>>(x_src, ei, et, E);

    dim3 gg((ND + BM - 1) / BM, D / BN);
    // layer 1: root from x_dst, write h (relu)
    gemm_kernel<<<gg, 256>>>(x_dst, w1, root1, b1, nullptr, 0, 1, 1);
    // layer 2: root from h, write d_out (no relu)
    gemm_kernel<<<gg, 256>>>(nullptr, w2, root2, b2, out, 1, 0, 0);
}

// round 2
// speedup vs baseline: 3.2848x; 3.2848x over previous
#include <cuda_runtime.h>
#include <cstdint>

constexpr int ND   = 30000;
constexpr int D    = 256;
constexpr int R    = 8;
constexpr int KW   = R * D;     // 2048
constexpr int KTOT = KW + D;    // 2304

constexpr int BM = 128, BN = 128, BK = 32;
constexpr int BKp = BK + 4;     // A smem stride (bank-spread)
constexpr int BNp = BN + 8;     // B smem stride (bank-spread)

// Scratch (no allocations allowed)
__device__ float g_sum[(size_t)ND * R * D];   // per-(dst,rel) sums
__device__ float g_cnt[ND * R];
__device__ float g_h[(size_t)ND * D];         // layer-1 activations

// ---------------------------------------------------------------------------
__device__ __forceinline__ uint32_t f2tf(float x) {
    uint32_t r; asm("cvt.rna.tf32.f32 %0, %1;" : "=r"(r) : "f"(x)); return r;
}
__device__ __forceinline__ void mma_tf32(float* c, const uint32_t* a, const uint32_t* b) {
    asm volatile(
        "mma.sync.aligned.m16n8k8.row.col.f32.tf32.tf32.f32 "
        "{%0,%1,%2,%3}, {%4,%5,%6,%7}, {%8,%9}, {%0,%1,%2,%3};"
        : "+f"(c[0]), "+f"(c[1]), "+f"(c[2]), "+f"(c[3])
        : "r"(a[0]), "r"(a[1]), "r"(a[2]), "r"(a[3]), "r"(b[0]), "r"(b[1]));
}

// ---------------------------------------------------------------------------
// Kernel 1: zero sums + counts
// ---------------------------------------------------------------------------
__global__ void zero_kernel() {
    size_t stride = (size_t)gridDim.x * blockDim.x;
    size_t i = (size_t)blockIdx.x * blockDim.x + threadIdx.x;
    float4 z = make_float4(0.f, 0.f, 0.f, 0.f);
    size_t nsum4 = (size_t)ND * R * D / 4;
    for (size_t j = i; j < nsum4; j += stride) ((float4*)g_sum)[j] = z;
    size_t ncnt4 = (size_t)ND * R / 4;
    for (size_t j = i; j < ncnt4; j += stride) ((float4*)g_cnt)[j] = z;
}

// ---------------------------------------------------------------------------
// Kernel 2: scatter-add (one warp per edge), vector red.global.add.v4.f32
// ---------------------------------------------------------------------------
__global__ void scatter_kernel(const float* __restrict__ x_src,
                               const void*  __restrict__ ei,
                               const void*  __restrict__ et,
                               int E) {
    int gw   = (blockIdx.x * blockDim.x + threadIdx.x) >> 5;
    int lane = threadIdx.x & 31;
    if (gw >= E) return;

    const int* ei32 = (const int*)ei;
    bool is64 = ((ei32[1] | ei32[3] | ei32[5] | ei32[7]) == 0);

    long long s, d, r;
    if (is64) {
        const long long* p = (const long long*)ei;
        s = p[gw]; d = p[E + gw]; r = ((const long long*)et)[gw];
    } else {
        s = ei32[gw]; d = ei32[E + gw]; r = ((const int*)et)[gw];
    }

    const float4* xr  = (const float4*)(x_src + (size_t)s * D);
    float4*       out = (float4*)(g_sum + ((size_t)d * R + r) * D);
#pragma unroll
    for (int it = 0; it < 2; it++) {
        float4 v = __ldg(xr + lane + 32 * it);
        asm volatile("red.global.add.v4.f32 [%0], {%1,%2,%3,%4};"
                     :: "l"(out + lane + 32 * it),
                        "f"(v.x), "f"(v.y), "f"(v.z), "f"(v.w) : "memory");
    }
    if (lane == 0) atomicAdd(&g_cnt[d * R + r], 1.0f);
}

// ---------------------------------------------------------------------------
// Kernel 3: tf32 tensor-core GEMM
//   C = [agg_scaled | A_root] @ [W ; Wroot] + bias (+relu)
//   CTA 128x128x32, 8 warps each 32(M)x64(N), mma.m16n8k8 tf32.
// ---------------------------------------------------------------------------
__global__ __launch_bounds__(256)
void gemm_kernel(const float* __restrict__ Aroot_ext,
                 const float* __restrict__ W,      // (2048,256) row-major
                 const float* __restrict__ Wroot,  // (256,256)
                 const float* __restrict__ bias,
                 float* __restrict__ Cout_ext,
                 int rootFromH, int writeH, int doRelu) {
    __shared__ __align__(16) uint32_t As[BM][BKp];
    __shared__ __align__(16) uint32_t Bs[BK][BNp];
    __shared__ float s_inv[BM * R];

    const float* Aroot = rootFromH ? g_h : Aroot_ext;
    float*       C     = writeH   ? g_h : Cout_ext;

    int tid  = threadIdx.x;
    int wid  = tid >> 5;
    int lane = tid & 31;
    int g    = lane >> 2;      // 0..7
    int t    = lane & 3;       // 0..3

    int row0 = blockIdx.y * BM;          // M tile (y = slow)
    int ncta = blockIdx.x;               // N tile (x = fast, shares A via L2)
    int wm   = (wid >> 1) * 32;          // warp M offset 0..96
    int wn   = (wid & 1) * 64;           // warp N offset 0/64

    // per-(row, relation) 1/max(cnt,1)
    for (int i = tid; i < BM * R; i += 256) {
        int rl = i >> 3, rr = i & 7;
        int grow = row0 + rl;
        float c = (grow < ND) ? g_cnt[grow * R + rr] : 1.0f;
        s_inv[i] = 1.0f / fmaxf(c, 1.0f);
    }
    __syncthreads();

    float acc[2][8][4];
#pragma unroll
    for (int mi = 0; mi < 2; mi++)
#pragma unroll
        for (int nj = 0; nj < 8; nj++)
#pragma unroll
            for (int q = 0; q < 4; q++) acc[mi][nj][q] = 0.f;

    for (int k0 = 0; k0 < KTOT; k0 += BK) {
        // ---- stage global -> regs (overlaps previous compute) ----
        float4 av[4]; float asc[4];
#pragma unroll
        for (int l = 0; l < 4; l++) {
            int f  = tid + l * 256;          // 1024 float4s = 128 x 32
            int rl = f >> 3;
            int c4 = (f & 7) << 2;
            int grow = row0 + rl;
            av[l] = make_float4(0.f, 0.f, 0.f, 0.f);
            asc[l] = 0.f;
            if (grow < ND) {
                if (k0 < KW) {
                    av[l]  = __ldg((const float4*)(g_sum + (size_t)grow * KW + k0 + c4));
                    asc[l] = s_inv[rl * R + ((k0 + c4) >> 8)];
                } else {
                    av[l]  = __ldg((const float4*)(Aroot + (size_t)grow * D + (k0 - KW) + c4));
                    asc[l] = 1.0f;
                }
            }
        }
        const float* Bsrc = (k0 < KW) ? (W + (size_t)k0 * D)
                                      : (Wroot + (size_t)(k0 - KW) * D);
        float4 bv[4];
#pragma unroll
        for (int l = 0; l < 4; l++) {
            int f  = tid + l * 256;          // 1024 float4s = 32 x 128
            int kr = f >> 5;
            int c4 = (f & 31) << 2;
            bv[l] = __ldg((const float4*)(Bsrc + (size_t)kr * D + ncta * BN + c4));
        }

        __syncthreads();   // previous tile fully consumed

        // ---- store to smem as tf32 ----
#pragma unroll
        for (int l = 0; l < 4; l++) {
            int f  = tid + l * 256;
            int rl = f >> 3;
            int c4 = (f & 7) << 2;
            As[rl][c4 + 0] = f2tf(av[l].x * asc[l]);
            As[rl][c4 + 1] = f2tf(av[l].y * asc[l]);
            As[rl][c4 + 2] = f2tf(av[l].z * asc[l]);
            As[rl][c4 + 3] = f2tf(av[l].w * asc[l]);
        }
#pragma unroll
        for (int l = 0; l < 4; l++) {
            int f  = tid + l * 256;
            int kr = f >> 5;
            int c4 = (f & 31) << 2;
            Bs[kr][c4 + 0] = f2tf(bv[l].x);
            Bs[kr][c4 + 1] = f2tf(bv[l].y);
            Bs[kr][c4 + 2] = f2tf(bv[l].z);
            Bs[kr][c4 + 3] = f2tf(bv[l].w);
        }
        __syncthreads();

        // ---- 4 k-steps of m16n8k8 ----
#pragma unroll
        for (int ks = 0; ks < 4; ks++) {
            int kb = ks * 8;
            uint32_t a[2][4];
#pragma unroll
            for (int mi = 0; mi < 2; mi++) {
                int rm = wm + mi * 16;
                a[mi][0] = As[rm + g    ][kb + t    ];
                a[mi][1] = As[rm + g + 8][kb + t    ];
                a[mi][2] = As[rm + g    ][kb + t + 4];
                a[mi][3] = As[rm + g + 8][kb + t + 4];
            }
#pragma unroll
            for (int nj = 0; nj < 8; nj++) {
                int cn = wn + nj * 8 + g;
                uint32_t b[2];
                b[0] = Bs[kb + t    ][cn];
                b[1] = Bs[kb + t + 4][cn];
                mma_tf32(acc[0][nj], a[0], b);
                mma_tf32(acc[1][nj], a[1], b);
            }
        }
    }

    // ---- epilogue: bias (+relu), float2 stores ----
#pragma unroll
    for (int mi = 0; mi < 2; mi++) {
        int r0g = row0 + wm + mi * 16 + g;
#pragma unroll
        for (int nj = 0; nj < 8; nj++) {
            int col = ncta * BN + wn + nj * 8 + 2 * t;
            float b0 = __ldg(&bias[col]);
            float b1 = __ldg(&bias[col + 1]);
            float2 o0 = make_float2(acc[mi][nj][0] + b0, acc[mi][nj][1] + b1);
            float2 o1 = make_float2(acc[mi][nj][2] + b0, acc[mi][nj][3] + b1);
            if (doRelu) {
                o0.x = fmaxf(o0.x, 0.f); o0.y = fmaxf(o0.y, 0.f);
                o1.x = fmaxf(o1.x, 0.f); o1.y = fmaxf(o1.y, 0.f);
            }
            if (r0g < ND)     *(float2*)(C + (size_t)r0g * D + col)       = o0;
            if (r0g + 8 < ND) *(float2*)(C + (size_t)(r0g + 8) * D + col) = o1;
        }
    }
}

// ---------------------------------------------------------------------------
extern "C" void kernel_launch(void* const* d_in, const int* in_sizes, int n_in,
                              void* d_out, int out_size) {
    const float* x_src = (const float*)d_in[0];
    const float* x_dst = (const float*)d_in[1];
    const void*  ei    = d_in[2];
    const void*  et    = d_in[3];
    const float* w1    = (const float*)d_in[4];
    const float* root1 = (const float*)d_in[5];
    const float* b1    = (const float*)d_in[6];
    const float* w2    = (const float*)d_in[7];
    const float* root2 = (const float*)d_in[8];
    const float* b2    = (const float*)d_in[9];
    float* out = (float*)d_out;
    int E = in_sizes[3];

    zero_kernel<<<2368, 256>>>();

    int nblk = (E + 7) / 8;   // 8 warps per 256-thread block
    scatter_kernel<<<nblk, 256>>>(x_src, ei, et, E);

    dim3 gg(D / BN, (ND + BM - 1) / BM);   // x = N tile (fast), y = M tile
    gemm_kernel<<<gg, 256>>>(x_dst, w1, root1, b1, nullptr, 0, 1, 1);
    gemm_kernel<<<gg, 256>>>(nullptr, w2, root2, b2, out, 1, 0, 0);
}

// round 3
// speedup vs baseline: 4.2588x; 1.2965x over previous
#include <cuda_runtime.h>
#include <cstdint>

constexpr int ND   = 30000;
constexpr int D    = 256;
constexpr int R    = 8;
constexpr int KW   = R * D;     // 2048
constexpr int KTOT = KW + D;    // 2304

// fused GEMM tiling
constexpr int BM = 64, BN = 128, BK = 32;
constexpr int BKp = 36;         // A smem stride
constexpr int BNp = 136;        // B smem stride
constexpr int NITER = KTOT / BK;   // 72

constexpr int AS_SZ = 2 * BM * BKp;        // u32 words
constexpr int BS_SZ = 2 * 2 * BK * BNp;    // u32 words
constexpr int SMEM_BYTES = (AS_SZ + BS_SZ + BM * R) * 4;   // 90112

// Scratch (no allocations allowed)
__device__ float    g_sum[(size_t)ND * R * D];
__device__ float    g_cnt[ND * R];
__device__ float    g_h[(size_t)ND * D];
__device__ uint32_t g_w1t[KTOT * D];   // [W1 ; root1] as tf32
__device__ uint32_t g_w2t[KTOT * D];   // [W2 ; zeros] as tf32
__device__ uint32_t g_r2t[D * D];      // root2 as tf32

// ---------------------------------------------------------------------------
__device__ __forceinline__ uint32_t f2tf(float x) {
    uint32_t r; asm("cvt.rna.tf32.f32 %0, %1;" : "=r"(r) : "f"(x)); return r;
}
__device__ __forceinline__ void mma_tf32(float* c, const uint32_t* a, const uint32_t* b) {
    asm volatile(
        "mma.sync.aligned.m16n8k8.row.col.f32.tf32.tf32.f32 "
        "{%0,%1,%2,%3}, {%4,%5,%6,%7}, {%8,%9}, {%0,%1,%2,%3};"
        : "+f"(c[0]), "+f"(c[1]), "+f"(c[2]), "+f"(c[3])
        : "r"(a[0]), "r"(a[1]), "r"(a[2]), "r"(a[3]), "r"(b[0]), "r"(b[1]));
}
__device__ __forceinline__ void cp_async16(uint32_t* smem_dst, const void* gsrc) {
    uint32_t s = (uint32_t)__cvta_generic_to_shared(smem_dst);
    asm volatile("cp.async.cg.shared.global [%0], [%1], 16;" :: "r"(s), "l"(gsrc));
}
#define CP_COMMIT() asm volatile("cp.async.commit_group;")
#define CP_WAIT0()  asm volatile("cp.async.wait_group 0;")

// ---------------------------------------------------------------------------
// Kernel 0: pre-convert weights to tf32 (and build concatenated/padded layouts)
// ---------------------------------------------------------------------------
__global__ void prep_kernel(const float* __restrict__ w1, const float* __restrict__ r1,
                            const float* __restrict__ w2, const float* __restrict__ r2) {
    int i = blockIdx.x * blockDim.x + threadIdx.x;
    if (i < KTOT * D) {
        float v1 = (i < KW * D) ? w1[i] : r1[i - KW * D];
        g_w1t[i] = f2tf(v1);
        g_w2t[i] = (i < KW * D) ? f2tf(w2[i]) : 0u;
    }
    if (i < D * D) g_r2t[i] = f2tf(r2[i]);
}

// ---------------------------------------------------------------------------
// Kernel 1: zero sums + counts
// ---------------------------------------------------------------------------
__global__ void zero_kernel() {
    size_t stride = (size_t)gridDim.x * blockDim.x;
    size_t i = (size_t)blockIdx.x * blockDim.x + threadIdx.x;
    float4 z = make_float4(0.f, 0.f, 0.f, 0.f);
    size_t nsum4 = (size_t)ND * R * D / 4;
    for (size_t j = i; j < nsum4; j += stride) ((float4*)g_sum)[j] = z;
    size_t ncnt4 = (size_t)ND * R / 4;
    for (size_t j = i; j < ncnt4; j += stride) ((float4*)g_cnt)[j] = z;
}

// ---------------------------------------------------------------------------
// Kernel 2: scatter-add (one warp per edge), red.global.add.v4.f32
// ---------------------------------------------------------------------------
__global__ void scatter_kernel(const float* __restrict__ x_src,
                               const void*  __restrict__ ei,
                               const void*  __restrict__ et,
                               int E) {
    int gw   = (blockIdx.x * blockDim.x + threadIdx.x) >> 5;
    int lane = threadIdx.x & 31;
    if (gw >= E) return;

    const int* ei32 = (const int*)ei;
    bool is64 = ((ei32[1] | ei32[3] | ei32[5] | ei32[7]) == 0);

    long long s, d, r;
    if (is64) {
        const long long* p = (const long long*)ei;
        s = p[gw]; d = p[E + gw]; r = ((const long long*)et)[gw];
    } else {
        s = ei32[gw]; d = ei32[E + gw]; r = ((const int*)et)[gw];
    }

    const float4* xr  = (const float4*)(x_src + (size_t)s * D);
    float4*       dst = (float4*)(g_sum + ((size_t)d * R + r) * D);
#pragma unroll
    for (int it = 0; it < 2; it++) {
        float4 v = __ldg(xr + lane + 32 * it);
        asm volatile("red.global.add.v4.f32 [%0], {%1,%2,%3,%4};"
                     :: "l"(dst + lane + 32 * it),
                        "f"(v.x), "f"(v.y), "f"(v.z), "f"(v.w) : "memory");
    }
    if (lane == 0) atomicAdd(&g_cnt[d * R + r], 1.0f);
}

// ---------------------------------------------------------------------------
// Kernel 3: FUSED dual-layer tf32 GEMM.
//   A = [agg_scaled | x_dst]  (ND x 2304), read ONCE.
//   acc1 = A @ [W1;root1]  -> h = relu(acc1 + b1)        -> g_h
//   acc2 = A @ [W2;0]      -> out_partial = acc2 + b2    -> d_out
// CTA 64x128, 8 warps as 2(M)x4(N), warp tile 32x32, double-buffered,
// cp.async B (pre-converted tf32), 1 __syncthreads per K-tile.
// ---------------------------------------------------------------------------
__global__ __launch_bounds__(256, 2)
void fused_gemm(const float* __restrict__ x_dst,
                const float* __restrict__ b1,
                const float* __restrict__ b2,
                float* __restrict__ out) {
    extern __shared__ uint32_t sm[];
    uint32_t* As  = sm;                    // [2][BM][BKp]
    uint32_t* Bsm = sm + AS_SZ;            // [2][2][BK][BNp]
    float*  s_inv = (float*)(sm + AS_SZ + BS_SZ);

    int tid  = threadIdx.x;
    int wid  = tid >> 5;
    int lane = tid & 31;
    int g    = lane >> 2;
    int t    = lane & 3;

    int row0 = blockIdx.y * BM;
    int ncta = blockIdx.x;
    int wm   = (wid >> 2) * 32;
    int wn   = (wid & 3) * 32;

    for (int i = tid; i < BM * R; i += 256) {
        int rl = i >> 3, rr = i & 7;
        int grow = row0 + rl;
        float c = (grow < ND) ? g_cnt[grow * R + rr] : 1.0f;
        s_inv[i] = 1.0f / fmaxf(c, 1.0f);
    }
    __syncthreads();

    float acc[2][2][4][4];
#pragma unroll
    for (int L = 0; L < 2; L++)
#pragma unroll
        for (int mi = 0; mi < 2; mi++)
#pragma unroll
            for (int nj = 0; nj < 4; nj++)
#pragma unroll
                for (int q = 0; q < 4; q++) acc[L][mi][nj][q] = 0.f;

    float4 av[2]; float asc[2];

    // --- A: global -> regs ---
    auto loadA = [&](int k0) {
#pragma unroll
        for (int l = 0; l < 2; l++) {
            int f  = tid + l * 256;            // 512 float4 = 64 x 32
            int rl = f >> 3;
            int c4 = (f & 7) << 2;
            int grow = row0 + rl;
            av[l] = make_float4(0.f, 0.f, 0.f, 0.f);
            asc[l] = 0.f;
            if (grow < ND) {
                if (k0 < KW) {
                    av[l]  = __ldg((const float4*)(g_sum + (size_t)grow * KW + k0 + c4));
                    asc[l] = s_inv[rl * R + (k0 >> 8)];
                } else {
                    av[l]  = __ldg((const float4*)(x_dst + (size_t)grow * D + (k0 - KW) + c4));
                    asc[l] = 1.0f;
                }
            }
        }
    };
    // --- A: regs -> smem (scale + tf32) ---
    auto storeA = [&](int stage) {
#pragma unroll
        for (int l = 0; l < 2; l++) {
            int f  = tid + l * 256;
            int rl = f >> 3;
            int c4 = (f & 7) << 2;
            uint4 w;
            w.x = f2tf(av[l].x * asc[l]);
            w.y = f2tf(av[l].y * asc[l]);
            w.z = f2tf(av[l].z * asc[l]);
            w.w = f2tf(av[l].w * asc[l]);
            *(uint4*)(As + stage * BM * BKp + rl * BKp + c4) = w;
        }
    };
    // --- B: cp.async both layers ---
    auto loadB = [&](int stage, int k0) {
#pragma unroll
        for (int l = 0; l < 4; l++) {
            int f  = tid + l * 256;            // 1024 16B chunks = 32 x 128 u32
            int kr = f >> 5;
            int c4 = (f & 31) << 2;
            size_t gofs = (size_t)(k0 + kr) * D + ncta * BN + c4;
            cp_async16(Bsm + ((stage * 2 + 0) * BK + kr) * BNp + c4, g_w1t + gofs);
            cp_async16(Bsm + ((stage * 2 + 1) * BK + kr) * BNp + c4, g_w2t + gofs);
        }
    };
    auto compute = [&](int stage) {
        uint32_t* Ab = As + stage * BM * BKp;
        uint32_t* B1 = Bsm + (stage * 2 + 0) * BK * BNp;
        uint32_t* B2 = Bsm + (stage * 2 + 1) * BK * BNp;
#pragma unroll
        for (int ks = 0; ks < 4; ks++) {
            int kb = ks * 8;
            uint32_t a[2][4];
#pragma unroll
            for (int mi = 0; mi < 2; mi++) {
                int rm = wm + mi * 16;
                a[mi][0] = Ab[(rm + g    ) * BKp + kb + t    ];
                a[mi][1] = Ab[(rm + g + 8) * BKp + kb + t    ];
                a[mi][2] = Ab[(rm + g    ) * BKp + kb + t + 4];
                a[mi][3] = Ab[(rm + g + 8) * BKp + kb + t + 4];
            }
#pragma unroll
            for (int nj = 0; nj < 4; nj++) {
                int cn = wn + nj * 8 + g;
                uint32_t bv1[2] = { B1[(kb + t) * BNp + cn], B1[(kb + t + 4) * BNp + cn] };
                uint32_t bv2[2] = { B2[(kb + t) * BNp + cn], B2[(kb + t + 4) * BNp + cn] };
                mma_tf32(acc[0][0][nj], a[0], bv1);
                mma_tf32(acc[0][1][nj], a[1], bv1);
                mma_tf32(acc[1][0][nj], a[0], bv2);
                mma_tf32(acc[1][1][nj], a[1], bv2);
            }
        }
    };

    // prologue
    loadB(0, 0); CP_COMMIT();
    loadA(0); storeA(0);
    CP_WAIT0();
    __syncthreads();

    for (int k = 0; k < NITER; k++) {
        int cur = k & 1, nxt = cur ^ 1;
        if (k + 1 < NITER) {
            loadB(nxt, (k + 1) * BK); CP_COMMIT();
            loadA((k + 1) * BK);
        }
        compute(cur);
        if (k + 1 < NITER) {
            CP_WAIT0();
            storeA(nxt);
        }
        __syncthreads();
    }

    // epilogue
#pragma unroll
    for (int mi = 0; mi < 2; mi++) {
        int r0g = row0 + wm + mi * 16 + g;
#pragma unroll
        for (int nj = 0; nj < 4; nj++) {
            int col = ncta * BN + wn + nj * 8 + 2 * t;
            float b1a = __ldg(&b1[col]), b1b = __ldg(&b1[col + 1]);
            float b2a = __ldg(&b2[col]), b2b = __ldg(&b2[col + 1]);
            float2 h0 = make_float2(fmaxf(acc[0][mi][nj][0] + b1a, 0.f),
                                    fmaxf(acc[0][mi][nj][1] + b1b, 0.f));
            float2 h1 = make_float2(fmaxf(acc[0][mi][nj][2] + b1a, 0.f),
                                    fmaxf(acc[0][mi][nj][3] + b1b, 0.f));
            float2 o0 = make_float2(acc[1][mi][nj][0] + b2a, acc[1][mi][nj][1] + b2b);
            float2 o1 = make_float2(acc[1][mi][nj][2] + b2a, acc[1][mi][nj][3] + b2b);
            if (r0g < ND) {
                *(float2*)(g_h + (size_t)r0g * D + col) = h0;
                *(float2*)(out + (size_t)r0g * D + col) = o0;
            }
            if (r0g + 8 < ND) {
                *(float2*)(g_h + (size_t)(r0g + 8) * D + col) = h1;
                *(float2*)(out + (size_t)(r0g + 8) * D + col) = o1;
            }
        }
    }
}

// ---------------------------------------------------------------------------
// Kernel 4: out += h @ root2   (M=30000, N=256, K=256)
// CTA 128x128x32, warp tile 32x64 (round-2 style, only 8 K-iters).
// ---------------------------------------------------------------------------
constexpr int RM = 128, RN = 128, RK = 32;
__global__ __launch_bounds__(256)
void root2_gemm(float* __restrict__ out) {
    __shared__ __align__(16) uint32_t As2[RM][RK + 4];
    __shared__ __align__(16) uint32_t Bs2[RK][RN + 8];

    int tid  = threadIdx.x;
    int wid  = tid >> 5;
    int lane = tid & 31;
    int g    = lane >> 2;
    int t    = lane & 3;

    int row0 = blockIdx.y * RM;
    int ncta = blockIdx.x;
    int wm   = (wid >> 1) * 32;
    int wn   = (wid & 1) * 64;

    float acc[2][8][4];
#pragma unroll
    for (int mi = 0; mi < 2; mi++)
#pragma unroll
        for (int nj = 0; nj < 8; nj++)
#pragma unroll
            for (int q = 0; q < 4; q++) acc[mi][nj][q] = 0.f;

    for (int k0 = 0; k0 < D; k0 += RK) {
        float4 avv[4]; uint4 bvv[4];
#pragma unroll
        for (int l = 0; l < 4; l++) {
            int f  = tid + l * 256;        // 1024 float4 = 128 x 32
            int rl = f >> 3;
            int c4 = (f & 7) << 2;
            int grow = row0 + rl;
            avv[l] = (grow < ND) ? __ldg((const float4*)(g_h + (size_t)grow * D + k0 + c4))
                                 : make_float4(0.f, 0.f, 0.f, 0.f);
        }
#pragma unroll
        for (int l = 0; l < 4; l++) {
            int f  = tid + l * 256;        // 1024 uint4 = 32 x 128
            int kr = f >> 5;
            int c4 = (f & 31) << 2;
            bvv[l] = __ldg((const uint4*)(g_r2t + (size_t)(k0 + kr) * D + ncta * RN + c4));
        }
        __syncthreads();
#pragma unroll
        for (int l = 0; l < 4; l++) {
            int f  = tid + l * 256;
            int rl = f >> 3;
            int c4 = (f & 7) << 2;
            As2[rl][c4 + 0] = f2tf(avv[l].x);
            As2[rl][c4 + 1] = f2tf(avv[l].y);
            As2[rl][c4 + 2] = f2tf(avv[l].z);
            As2[rl][c4 + 3] = f2tf(avv[l].w);
        }
#pragma unroll
        for (int l = 0; l < 4; l++) {
            int f  = tid + l * 256;
            int kr = f >> 5;
            int c4 = (f & 31) << 2;
            *(uint4*)&Bs2[kr][c4] = bvv[l];
        }
        __syncthreads();

#pragma unroll
        for (int ks = 0; ks < 4; ks++) {
            int kb = ks * 8;
            uint32_t a[2][4];
#pragma unroll
            for (int mi = 0; mi < 2; mi++) {
                int rm = wm + mi * 16;
                a[mi][0] = As2[rm + g    ][kb + t    ];
                a[mi][1] = As2[rm + g + 8][kb + t    ];
                a[mi][2] = As2[rm + g    ][kb + t + 4];
                a[mi][3] = As2[rm + g + 8][kb + t + 4];
            }
#pragma unroll
            for (int nj = 0; nj < 8; nj++) {
                int cn = wn + nj * 8 + g;
                uint32_t b[2] = { Bs2[kb + t][cn], Bs2[kb + t + 4][cn] };
                mma_tf32(acc[0][nj], a[0], b);
                mma_tf32(acc[1][nj], a[1], b);
            }
        }
        __syncthreads();
    }

#pragma unroll
    for (int mi = 0; mi < 2; mi++) {
        int r0g = row0 + wm + mi * 16 + g;
#pragma unroll
        for (int nj = 0; nj < 8; nj++) {
            int col = ncta * RN + wn + nj * 8 + 2 * t;
            if (r0g < ND) {
                float2* p = (float2*)(out + (size_t)r0g * D + col);
                float2 o = *p;
                o.x += acc[mi][nj][0]; o.y += acc[mi][nj][1];
                *p = o;
            }
            if (r0g + 8 < ND) {
                float2* p = (float2*)(out + (size_t)(r0g + 8) * D + col);
                float2 o = *p;
                o.x += acc[mi][nj][2]; o.y += acc[mi][nj][3];
                *p = o;
            }
        }
    }
}

// ---------------------------------------------------------------------------
extern "C" void kernel_launch(void* const* d_in, const int* in_sizes, int n_in,
                              void* d_out, int out_size) {
    const float* x_src = (const float*)d_in[0];
    const float* x_dst = (const float*)d_in[1];
    const void*  ei    = d_in[2];
    const void*  et    = d_in[3];
    const float* w1    = (const float*)d_in[4];
    const float* root1 = (const float*)d_in[5];
    const float* b1    = (const float*)d_in[6];
    const float* w2    = (const float*)d_in[7];
    const float* root2 = (const float*)d_in[8];
    const float* b2    = (const float*)d_in[9];
    float* out = (float*)d_out;
    int E = in_sizes[3];

    cudaFuncSetAttribute(fused_gemm, cudaFuncAttributeMaxDynamicSharedMemorySize, SMEM_BYTES);

    prep_kernel<<<(KTOT * D + 255) / 256, 256>>>(w1, root1, w2, root2);
    zero_kernel<<<2368, 256>>>();
    scatter_kernel<<<(E + 7) / 8, 256>>>(x_src, ei, et, E);

    dim3 gg(D / BN, (ND + BM - 1) / BM);        // (2, 469)
    fused_gemm<<<gg, 256, SMEM_BYTES>>>(x_dst, b1, b2, out);

    dim3 g2(D / RN, (ND + RM - 1) / RM);        // (2, 235)
    root2_gemm<<<g2, 256>>>(out);
}

// round 5
// speedup vs baseline: 5.2034x; 1.2218x over previous
#include <cuda_runtime.h>
#include <cuda_fp16.h>
#include <cstdint>

constexpr int ND = 30000, D = 256, R = 8, KW = 2048;
constexpr int NC    = 72;                       // main K chunks of 32
constexpr int MTILE = 64;
constexpr int GRID_M = (ND + MTILE - 1) / MTILE;  // 469

// smem layout (bytes)
constexpr int SINV_OFF = 0;                     // 512 floats
constexpr int A_OFF    = 2048;                  // 2 stages x [64 rows][36 halfs]
constexpr int A_STAGE  = 64 * 72;               // 4608
constexpr int B_OFF    = A_OFF + 2 * A_STAGE;   // 11264
constexpr int B_STAGE  = 512 * 80;              // 40960 (rows padded to 80B)
constexpr int H_OFF    = B_OFF + 2 * B_STAGE;   // 93184
constexpr int H_STRIDE = 528;                   // 264 halfs per row
constexpr int SMEM_T   = H_OFF + 64 * H_STRIDE; // 126976

// device scratch (no allocations allowed)
__device__ float  g_sum[(size_t)ND * KW];
__device__ float  g_cnt[ND * R];
__device__ __half g_Bh[(size_t)2 * NC * 256 * 32];  // [L][kc][n(512/2)][k32] fp16
__device__ __half g_r2h[256 * 256];                 // root2 transposed [n][k] fp16

// ---------------------------------------------------------------------------
__device__ __forceinline__ void mma_f16(float* c, const uint32_t* a,
                                        uint32_t b0, uint32_t b1) {
    asm volatile(
        "mma.sync.aligned.m16n8k16.row.col.f32.f16.f16.f32 "
        "{%0,%1,%2,%3}, {%4,%5,%6,%7}, {%8,%9}, {%0,%1,%2,%3};"
        : "+f"(c[0]), "+f"(c[1]), "+f"(c[2]), "+f"(c[3])
        : "r"(a[0]), "r"(a[1]), "r"(a[2]), "r"(a[3]), "r"(b0), "r"(b1));
}
__device__ __forceinline__ void cp_async16(void* smem_dst, const void* gsrc) {
    uint32_t s = (uint32_t)__cvta_generic_to_shared(smem_dst);
    asm volatile("cp.async.cg.shared.global [%0], [%1], 16;" :: "r"(s), "l"(gsrc));
}
#define CP_COMMIT() asm volatile("cp.async.commit_group;")
#define CP_WAIT0()  asm volatile("cp.async.wait_group 0;")

// ---------------------------------------------------------------------------
// Kernel 0: prep — fp16 transposed weights [n][k] per 32-K chunk; root2 [n][k].
// ---------------------------------------------------------------------------
__global__ void prep_kernel(const float* __restrict__ w1, const float* __restrict__ r1,
                            const float* __restrict__ w2, const float* __restrict__ r2) {
    int gid = blockIdx.x * blockDim.x + threadIdx.x;
    if (gid < 2 * NC * 256 * 4) {
        int L   = gid / (NC * 256 * 4);
        int rem = gid % (NC * 256 * 4);
        int kc  = rem >> 10;
        int n   = (rem >> 2) & 255;
        int c8  = rem & 3;
        __half h8[8];
#pragma unroll
        for (int j = 0; j < 8; j++) {
            int k = kc * 32 + c8 * 8 + j;
            float x;
            if (L == 0) x = (k < KW) ? w1[(size_t)k * D + n] : r1[(size_t)(k - KW) * D + n];
            else        x = (k < KW) ? w2[(size_t)k * D + n] : 0.f;
            h8[j] = __float2half_rn(x);
        }
        *(uint4*)(g_Bh + ((size_t)(L * NC + kc) * 256 + n) * 32 + c8 * 8) = *(uint4*)h8;
    }
    if (gid < 256 * 32) {
        int n = gid >> 5, c8 = gid & 31;
        __half h8[8];
#pragma unroll
        for (int j = 0; j < 8; j++)
            h8[j] = __float2half_rn(r2[(size_t)(c8 * 8 + j) * 256 + n]);
        *(uint4*)(g_r2h + (size_t)n * 256 + c8 * 8) = *(uint4*)h8;
    }
}

// ---------------------------------------------------------------------------
// Kernel 1: zero sums + counts
// ---------------------------------------------------------------------------
__global__ void zero_kernel() {
    size_t stride = (size_t)gridDim.x * blockDim.x;
    size_t i = (size_t)blockIdx.x * blockDim.x + threadIdx.x;
    float4 z = make_float4(0.f, 0.f, 0.f, 0.f);
    size_t nsum4 = (size_t)ND * KW / 4;
    for (size_t j = i; j < nsum4; j += stride) ((float4*)g_sum)[j] = z;
    size_t ncnt4 = (size_t)ND * R / 4;
    for (size_t j = i; j < ncnt4; j += stride) ((float4*)g_cnt)[j] = z;
}

// ---------------------------------------------------------------------------
// Kernel 2: scatter-add (one warp per edge), red.global.add.v4.f32
// ---------------------------------------------------------------------------
__global__ void scatter_kernel(const float* __restrict__ x_src,
                               const void*  __restrict__ ei,
                               const void*  __restrict__ et,
                               int E) {
    int gw   = (blockIdx.x * blockDim.x + threadIdx.x) >> 5;
    int lane = threadIdx.x & 31;
    if (gw >= E) return;

    const int* ei32 = (const int*)ei;
    bool is64 = ((ei32[1] | ei32[3] | ei32[5] | ei32[7]) == 0);

    long long s, d, r;
    if (is64) {
        const long long* p = (const long long*)ei;
        s = p[gw]; d = p[E + gw]; r = ((const long long*)et)[gw];
    } else {
        s = ei32[gw]; d = ei32[E + gw]; r = ((const int*)et)[gw];
    }

    const float4* xr  = (const float4*)(x_src + (size_t)s * D);
    float4*       dst = (float4*)(g_sum + ((size_t)d * R + r) * D);
#pragma unroll
    for (int it = 0; it < 2; it++) {
        float4 v = __ldg(xr + lane + 32 * it);
        asm volatile("red.global.add.v4.f32 [%0], {%1,%2,%3,%4};"
                     :: "l"(dst + lane + 32 * it),
                        "f"(v.x), "f"(v.y), "f"(v.z), "f"(v.w) : "memory");
    }
    if (lane == 0) atomicAdd(&g_cnt[d * R + r], 1.0f);
}

// ---------------------------------------------------------------------------
// Kernel 3: fully-fused fp16 GEMM:
//   A = [agg_scaled | x_dst] (64-row tile, read once)
//   warps 0-3: layer1 -> h (relu) in smem; warps 4-7: layer2
//   then layer2 acc += h @ root2 (local), store out.
// ---------------------------------------------------------------------------
__global__ __launch_bounds__(256, 1)
void fused_all(const float* __restrict__ x_dst,
               const float* __restrict__ b1,
               const float* __restrict__ b2,
               float* __restrict__ out) {
    extern __shared__ char sm[];
    float* s_inv = (float*)(sm + SINV_OFF);

    int tid = threadIdx.x, wid = tid >> 5, lane = tid & 31;
    int g = lane >> 2, t = lane & 3;
    int L  = wid >> 2;          // 0 = layer1, 1 = layer2
    int cb = (wid & 3) * 64;    // 64-col group within layer

    int row0 = blockIdx.x * MTILE;

    for (int i = tid; i < MTILE * R; i += 256) {
        int rl = i >> 3, rr = i & 7;
        int grow = row0 + rl;
        float c = (grow < ND) ? g_cnt[grow * R + rr] : 1.0f;
        s_inv[i] = 1.0f / fmaxf(c, 1.0f);
    }
    __syncthreads();

    float acc[4][8][4];
#pragma unroll
    for (int mi = 0; mi < 4; mi++)
#pragma unroll
        for (int nj = 0; nj < 8; nj++)
#pragma unroll
            for (int q = 0; q < 4; q++) acc[mi][nj][q] = 0.f;

    float4 av[2]; float asc[2];
    auto ldA = [&](int kc) {
#pragma unroll
        for (int l = 0; l < 2; l++) {
            int f  = tid + l * 256;        // 512 float4 = 64 rows x 8
            int rl = f >> 3, c16 = f & 7;
            int grow = row0 + rl;
            av[l] = make_float4(0.f, 0.f, 0.f, 0.f);
            asc[l] = 0.f;
            if (grow < ND) {
                if (kc < 64) {
                    av[l]  = __ldg((const float4*)(g_sum + (size_t)grow * KW + kc * 32 + c16 * 4));
                    asc[l] = s_inv[rl * R + (kc >> 3)];
                } else {
                    av[l]  = __ldg((const float4*)(x_dst + (size_t)grow * D + (kc - 64) * 32 + c16 * 4));
                    asc[l] = 1.0f;
                }
            }
        }
    };
    auto stA = [&](int s) {
#pragma unroll
        for (int l = 0; l < 2; l++) {
            int f  = tid + l * 256;
            int rl = f >> 3, c16 = f & 7;
            __half h4[4];
            h4[0] = __float2half_rn(av[l].x * asc[l]);
            h4[1] = __float2half_rn(av[l].y * asc[l]);
            h4[2] = __float2half_rn(av[l].z * asc[l]);
            h4[3] = __float2half_rn(av[l].w * asc[l]);
            *(uint2*)(sm + A_OFF + s * A_STAGE + rl * 72 + c16 * 8) = *(uint2*)h4;
        }
    };
    auto ldB = [&](int kc, int s) {
        const __half* src = g_Bh + (size_t)kc * 256 * 32;   // layer stride NC*256*32
#pragma unroll
        for (int i = 0; i < 8; i++) {
            int idx = tid + i * 256;       // 2048 chunks: n = idx>>2, c = idx&3
            int n = idx >> 2, cc = idx & 3;
            const __half* gsrc = src + ((size_t)(n >> 8) * NC * 256 + (n & 255)) * 32 + cc * 8;
            cp_async16(sm + B_OFF + s * B_STAGE + n * 80 + cc * 16, gsrc);
        }
    };
    auto ldRootB = [&](int c, int s) {
#pragma unroll
        for (int i = 0; i < 8; i++) {
            int idx = tid + i * 256;       // 2048 chunks: 256 rows x 8
            int n = idx >> 3, cc = idx & 7;
            cp_async16(sm + B_OFF + s * B_STAGE + n * 144 + cc * 16,
                       g_r2h + (size_t)n * 256 + c * 64 + cc * 8);
        }
    };
    auto compute = [&](int s) {
        const char* Ab = sm + A_OFF + s * A_STAGE;
        const char* Bb = sm + B_OFF + s * B_STAGE;
#pragma unroll
        for (int ks = 0; ks < 2; ks++) {
            int kb = ks * 16;
            uint32_t a[4][4];
#pragma unroll
            for (int mi = 0; mi < 4; mi++) {
                const char* ar = Ab + (mi * 16 + g) * 72 + kb * 2 + t * 4;
                a[mi][0] = *(const uint32_t*)ar;
                a[mi][1] = *(const uint32_t*)(ar + 8 * 72);
                a[mi][2] = *(const uint32_t*)(ar + 16);
                a[mi][3] = *(const uint32_t*)(ar + 8 * 72 + 16);
            }
#pragma unroll
            for (int nj = 0; nj < 8; nj++) {
                int n = L * 256 + cb + nj * 8 + g;
                const char* br = Bb + n * 80 + kb * 2 + t * 4;
                uint32_t b0 = *(const uint32_t*)br;
                uint32_t b1v = *(const uint32_t*)(br + 16);
#pragma unroll
                for (int mi = 0; mi < 4; mi++) mma_f16(acc[mi][nj], a[mi], b0, b1v);
            }
        }
    };

    // ---- main loop: 72 chunks, double-buffered ----
    ldB(0, 0); CP_COMMIT();
    ldA(0); stA(0);
    CP_WAIT0();
    __syncthreads();

    for (int k = 0; k < NC; k++) {
        int s = k & 1;
        if (k + 1 < NC) { ldB(k + 1, s ^ 1); CP_COMMIT(); ldA(k + 1); }
        else            { ldRootB(0, 0); CP_COMMIT(); }
        compute(s);
        if (k + 1 < NC) { CP_WAIT0(); stA(s ^ 1); }
        __syncthreads();
    }

    // ---- layer1 epilogue: h = relu(acc + b1) -> smem fp16 ----
    if (L == 0) {
#pragma unroll
        for (int mi = 0; mi < 4; mi++) {
#pragma unroll
            for (int nj = 0; nj < 8; nj++) {
                int col = cb + nj * 8 + 2 * t;
                float ba = __ldg(&b1[col]), bb = __ldg(&b1[col + 1]);
                __half2 h0 = __floats2half2_rn(fmaxf(acc[mi][nj][0] + ba, 0.f),
                                               fmaxf(acc[mi][nj][1] + bb, 0.f));
                __half2 h1 = __floats2half2_rn(fmaxf(acc[mi][nj][2] + ba, 0.f),
                                               fmaxf(acc[mi][nj][3] + bb, 0.f));
                *(__half2*)(sm + H_OFF + (mi * 16 + g) * H_STRIDE + col * 2)     = h0;
                *(__half2*)(sm + H_OFF + (mi * 16 + g + 8) * H_STRIDE + col * 2) = h1;
            }
        }
    }
    __syncthreads();

    // ---- root phase: layer2 acc += h @ root2 (4 chunks of K=64) ----
    for (int c = 0; c < 4; c++) {
        int s = c & 1;
        CP_WAIT0();
        __syncthreads();
        if (c + 1 < 4) { ldRootB(c + 1, s ^ 1); CP_COMMIT(); }
        if (L == 1) {
            const char* Bb = sm + B_OFF + s * B_STAGE;
#pragma unroll
            for (int ks = 0; ks < 4; ks++) {
                uint32_t a[4][4];
#pragma unroll
                for (int mi = 0; mi < 4; mi++) {
                    const char* ar = sm + H_OFF + (mi * 16 + g) * H_STRIDE
                                     + (c * 64 + ks * 16) * 2 + t * 4;
                    a[mi][0] = *(const uint32_t*)ar;
                    a[mi][1] = *(const uint32_t*)(ar + 8 * H_STRIDE);
                    a[mi][2] = *(const uint32_t*)(ar + 16);
                    a[mi][3] = *(const uint32_t*)(ar + 8 * H_STRIDE + 16);
                }
#pragma unroll
                for (int nj = 0; nj < 8; nj++) {
                    int n = cb + nj * 8 + g;
                    const char* br = Bb + n * 144 + ks * 32 + t * 4;
                    uint32_t b0 = *(const uint32_t*)br;
                    uint32_t b1v = *(const uint32_t*)(br + 16);
#pragma unroll
                    for (int mi = 0; mi < 4; mi++) mma_f16(acc[mi][nj], a[mi], b0, b1v);
                }
            }
        }
        __syncthreads();
    }

    // ---- layer2 final store ----
    if (L == 1) {
#pragma unroll
        for (int mi = 0; mi < 4; mi++) {
            int r0g = row0 + mi * 16 + g;
#pragma unroll
            for (int nj = 0; nj < 8; nj++) {
                int col = cb + nj * 8 + 2 * t;
                float ba = __ldg(&b2[col]), bb = __ldg(&b2[col + 1]);
                if (r0g < ND)
                    *(float2*)(out + (size_t)r0g * D + col) =
                        make_float2(acc[mi][nj][0] + ba, acc[mi][nj][1] + bb);
                if (r0g + 8 < ND)
                    *(float2*)(out + (size_t)(r0g + 8) * D + col) =
                        make_float2(acc[mi][nj][2] + ba, acc[mi][nj][3] + bb);
            }
        }
    }
}

// ---------------------------------------------------------------------------
extern "C" void kernel_launch(void* const* d_in, const int* in_sizes, int n_in,
                              void* d_out, int out_size) {
    const float* x_src = (const float*)d_in[0];
    const float* x_dst = (const float*)d_in[1];
    const void*  ei    = d_in[2];
    const void*  et    = d_in[3];
    const float* w1    = (const float*)d_in[4];
    const float* root1 = (const float*)d_in[5];
    const float* b1    = (const float*)d_in[6];
    const float* w2    = (const float*)d_in[7];
    const float* root2 = (const float*)d_in[8];
    const float* b2    = (const float*)d_in[9];
    float* out = (float*)d_out;
    int E = in_sizes[3];

    cudaFuncSetAttribute(fused_all, cudaFuncAttributeMaxDynamicSharedMemorySize, SMEM_T);

    prep_kernel<<<(2 * NC * 256 * 4 + 255) / 256, 256>>>(w1, root1, w2, root2);
    zero_kernel<<<2368, 256>>>();
    scatter_kernel<<<(E + 7) / 8, 256>>>(x_src, ei, et, E);

    fused_all<<<GRID_M, 256, SMEM_T>>>(x_dst, b1, b2, out);
}

// round 8
// speedup vs baseline: 5.5630x; 1.0691x over previous
#include <cuda_runtime.h>
#include <cuda_fp16.h>
#include <cstdint>

constexpr int ND = 30000, D = 256, R = 8, KW = 2048;
constexpr int NC     = 72;                    // K chunks of 32 (2304/32)
constexpr int MTILE  = 64;
constexpr int GRID_M = (ND + MTILE - 1) / MTILE;   // 469
constexpr int THREADS = 512;
constexpr int NSB    = 4;                     // B pipeline stages (4 => no reuse race)

// smem layout (bytes)
constexpr int SINV_OFF = 0;                   // 512 floats
constexpr int A_OFF    = 2048;
constexpr int A_STAGE  = 64 * 72;             // 4608
constexpr int B_OFF    = A_OFF + 2 * A_STAGE; // 11264
constexpr int B_STAGE  = 512 * 80;            // 40960
constexpr int H_OFF    = B_OFF + NSB * B_STAGE;   // 175104
constexpr int H_STRIDE = 528;
constexpr int SMEM_T   = H_OFF + 64 * H_STRIDE;   // 208896

// device scratch (no allocations allowed)
__device__ float  g_sum[(size_t)ND * KW];          // f32 per-(dst,rel) sums (proven)
__device__ float  g_cnt[ND * R];
__device__ __half g_Bh[(size_t)2 * NC * 256 * 32]; // [L][kc][n][k32] fp16
__device__ __half g_r2h[256 * 256];                // root2 transposed [n][k]

// ---------------------------------------------------------------------------
__device__ __forceinline__ void mma_f16(float* c, const uint32_t* a,
                                        uint32_t b0, uint32_t b1) {
    asm volatile(
        "mma.sync.aligned.m16n8k16.row.col.f32.f16.f16.f32 "
        "{%0,%1,%2,%3}, {%4,%5,%6,%7}, {%8,%9}, {%0,%1,%2,%3};"
        : "+f"(c[0]), "+f"(c[1]), "+f"(c[2]), "+f"(c[3])
        : "r"(a[0]), "r"(a[1]), "r"(a[2]), "r"(a[3]), "r"(b0), "r"(b1));
}
__device__ __forceinline__ void cp_async16(void* smem_dst, const void* gsrc) {
    uint32_t s = (uint32_t)__cvta_generic_to_shared(smem_dst);
    asm volatile("cp.async.cg.shared.global [%0], [%1], 16;" :: "r"(s), "l"(gsrc));
}
#define CP_COMMIT() asm volatile("cp.async.commit_group;" ::: "memory")
#define CP_WAIT(n)  asm volatile("cp.async.wait_group %0;" :: "n"(n) : "memory")

// ---------------------------------------------------------------------------
// Kernel 0: prep — fp16 weights [n][k] chunks, root2 [n][k]
// ---------------------------------------------------------------------------
__global__ void prep_kernel(const float* __restrict__ w1, const float* __restrict__ r1,
                            const float* __restrict__ w2, const float* __restrict__ r2) {
    int gid = blockIdx.x * blockDim.x + threadIdx.x;
    if (gid < 2 * NC * 256 * 4) {
        int L   = gid / (NC * 256 * 4);
        int rem = gid % (NC * 256 * 4);
        int kc  = rem >> 10;
        int n   = (rem >> 2) & 255;
        int c8  = rem & 3;
        __half h8[8];
#pragma unroll
        for (int j = 0; j < 8; j++) {
            int k = kc * 32 + c8 * 8 + j;
            float x;
            if (L == 0) x = (k < KW) ? w1[(size_t)k * D + n] : r1[(size_t)(k - KW) * D + n];
            else        x = (k < KW) ? w2[(size_t)k * D + n] : 0.f;
            h8[j] = __float2half_rn(x);
        }
        *(uint4*)(g_Bh + ((size_t)(L * NC + kc) * 256 + n) * 32 + c8 * 8) = *(uint4*)h8;
    }
    if (gid < 256 * 32) {
        int n = gid >> 5, c8 = gid & 31;
        __half h8[8];
#pragma unroll
        for (int j = 0; j < 8; j++)
            h8[j] = __float2half_rn(r2[(size_t)(c8 * 8 + j) * 256 + n]);
        *(uint4*)(g_r2h + (size_t)n * 256 + c8 * 8) = *(uint4*)h8;
    }
}

// ---------------------------------------------------------------------------
// Kernel 1: zero f32 sums + counts
// ---------------------------------------------------------------------------
__global__ void zero_kernel() {
    size_t stride = (size_t)gridDim.x * blockDim.x;
    size_t i = (size_t)blockIdx.x * blockDim.x + threadIdx.x;
    float4 z = make_float4(0.f, 0.f, 0.f, 0.f);
    size_t nsum4 = (size_t)ND * KW / 4;
    for (size_t j = i; j < nsum4; j += stride) ((float4*)g_sum)[j] = z;
    size_t ncnt4 = (size_t)ND * R / 4;
    for (size_t j = i; j < ncnt4; j += stride) ((float4*)g_cnt)[j] = z;
}

// ---------------------------------------------------------------------------
// Kernel 2: f32 scatter-add (one warp per edge)
// ---------------------------------------------------------------------------
__global__ void scatter_kernel(const float* __restrict__ x_src,
                               const void*  __restrict__ ei,
                               const void*  __restrict__ et, int E) {
    int gw   = (blockIdx.x * blockDim.x + threadIdx.x) >> 5;
    int lane = threadIdx.x & 31;
    if (gw >= E) return;

    const int* ei32 = (const int*)ei;
    bool is64 = ((ei32[1] | ei32[3] | ei32[5] | ei32[7]) == 0);

    long long s, d, r;
    if (is64) {
        const long long* p = (const long long*)ei;
        s = p[gw]; d = p[E + gw]; r = ((const long long*)et)[gw];
    } else {
        s = ei32[gw]; d = ei32[E + gw]; r = ((const int*)et)[gw];
    }

    const float4* xr  = (const float4*)(x_src + (size_t)s * D);
    float4*       dst = (float4*)(g_sum + ((size_t)d * R + r) * D);
#pragma unroll
    for (int it = 0; it < 2; it++) {
        float4 v = __ldg(xr + lane + 32 * it);
        asm volatile("red.global.add.v4.f32 [%0], {%1,%2,%3,%4};"
                     :: "l"(dst + lane + 32 * it),
                        "f"(v.x), "f"(v.y), "f"(v.z), "f"(v.w) : "memory");
    }
    if (lane == 0) atomicAdd(&g_cnt[d * R + r], 1.0f);
}

// ---------------------------------------------------------------------------
// Kernel 3: fully-fused fp16 GEMM, 512 threads, 4-stage B pipeline.
//   warps 0-7: layer1 -> h (relu) in smem; warps 8-15: layer2 (+ h@root2)
// ---------------------------------------------------------------------------
__global__ __launch_bounds__(THREADS, 1)
void fused_all(const float* __restrict__ x_dst,
               const float* __restrict__ b1,
               const float* __restrict__ b2,
               float* __restrict__ out) {
    extern __shared__ char smx[];
    float* s_inv = (float*)(smx + SINV_OFF);

    int tid = threadIdx.x, wid = tid >> 5, lane = tid & 31;
    int g = lane >> 2, t = lane & 3;
    int L = wid >> 3, sub = wid & 7;
    int wm = (sub >> 2) * 32;       // 0 / 32
    int cb = (sub & 3) * 64;        // 0 / 64 / 128 / 192
    int row0 = blockIdx.x * MTILE;

    {
        int i = tid;                // MTILE*R == 512 == THREADS
        int rl = i >> 3, rr = i & 7, grow = row0 + rl;
        float c = (grow < ND) ? g_cnt[grow * R + rr] : 1.0f;
        s_inv[i] = 1.0f / fmaxf(c, 1.0f);
    }
    __syncthreads();

    float acc[2][8][4];
#pragma unroll
    for (int mi = 0; mi < 2; mi++)
#pragma unroll
        for (int nj = 0; nj < 8; nj++)
#pragma unroll
            for (int q = 0; q < 4; q++) acc[mi][nj][q] = 0.f;

    float4 av; float asc;
    auto ldA = [&](int kc) {
        int rl = tid >> 3, c4 = (tid & 7) << 2;
        int grow = row0 + rl;
        av = make_float4(0.f, 0.f, 0.f, 0.f);
        asc = 0.f;
        if (grow < ND) {
            if (kc < 64) {
                av  = __ldg((const float4*)(g_sum + (size_t)grow * KW + kc * 32 + c4));
                asc = s_inv[rl * R + (kc >> 3)];
            } else {
                av  = __ldg((const float4*)(x_dst + (size_t)grow * D + (kc - 64) * 32 + c4));
                asc = 1.0f;
            }
        }
    };
    auto stA = [&](int s) {
        int rl = tid >> 3, c16 = tid & 7;
        __half h4[4];
        h4[0] = __float2half_rn(av.x * asc);
        h4[1] = __float2half_rn(av.y * asc);
        h4[2] = __float2half_rn(av.z * asc);
        h4[3] = __float2half_rn(av.w * asc);
        *(uint2*)(smx + A_OFF + s * A_STAGE + rl * 72 + c16 * 8) = *(uint2*)h4;
    };
    auto ldB = [&](int kc, int s) {
#pragma unroll
        for (int i = 0; i < 4; i++) {
            int idx = tid + i * 512;
            int n5 = idx >> 2, c = idx & 3;
            int Lx = n5 >> 8, n = n5 & 255;
            cp_async16(smx + B_OFF + s * B_STAGE + n5 * 80 + c * 16,
                       g_Bh + ((size_t)(Lx * NC + kc) * 256 + n) * 32 + c * 8);
        }
    };
    auto ldRootB = [&](int c, int s) {
#pragma unroll
        for (int i = 0; i < 4; i++) {
            int idx = tid + i * 512;
            int n = idx >> 3, cc = idx & 7;
            cp_async16(smx + B_OFF + s * B_STAGE + n * 144 + cc * 16,
                       g_r2h + (size_t)n * 256 + c * 64 + cc * 8);
        }
    };
    auto compute = [&](int sA, int sB) {
        const char* Ab = smx + A_OFF + sA * A_STAGE;
        const char* Bb = smx + B_OFF + sB * B_STAGE;
#pragma unroll
        for (int ks = 0; ks < 2; ks++) {
            int kb = ks * 16;
            uint32_t a[2][4];
#pragma unroll
            for (int mi = 0; mi < 2; mi++) {
                const char* ar = Ab + (wm + mi * 16 + g) * 72 + kb * 2 + t * 4;
                a[mi][0] = *(const uint32_t*)ar;
                a[mi][1] = *(const uint32_t*)(ar + 8 * 72);
                a[mi][2] = *(const uint32_t*)(ar + 16);
                a[mi][3] = *(const uint32_t*)(ar + 8 * 72 + 16);
            }
#pragma unroll
            for (int nj = 0; nj < 8; nj++) {
                int n5 = L * 256 + cb + nj * 8 + g;
                const char* br = Bb + n5 * 80 + kb * 2 + t * 4;
                uint32_t b0  = *(const uint32_t*)br;
                uint32_t b1v = *(const uint32_t*)(br + 16);
                mma_f16(acc[0][nj], a[0], b0, b1v);
                mma_f16(acc[1][nj], a[1], b0, b1v);
            }
        }
    };

    // ---- main loop: 72 chunks; B 4-stage cp.async (k+2 lookahead) ----
    // Safety: writer at iter k+1 targets stage (k+3)%4; live readers are
    // stages k%4 and (k+1)%4 — disjoint for NSB=4. A double-buffer is safe
    // because stA executes after the iteration barrier.
    ldB(0, 0); CP_COMMIT();
    ldB(1, 1); CP_COMMIT();
    ldA(0); stA(0);

    for (int k = 0; k < NC; k++) {
        int sA = k & 1, sB = k % NSB;
        if (k + 2 < NC) ldB(k + 2, (k + 2) % NSB);
        CP_COMMIT();                 // empty groups pad the tail
        if (k + 1 < NC) ldA(k + 1);  // LDG in flight across barrier + compute
        CP_WAIT(2);                  // B chunk k resident
        __syncthreads();             // A chunk k (stored last iter) visible
        compute(sA, sB);
        if (k + 1 < NC) stA(sA ^ 1); // writes the stage NOT being read
    }
    __syncthreads();

    // ---- root2 prologue + layer1 epilogue (h -> smem, fp16) ----
    ldRootB(0, 0); CP_COMMIT();
    if (L == 0) {
#pragma unroll
        for (int mi = 0; mi < 2; mi++) {
#pragma unroll
            for (int nj = 0; nj < 8; nj++) {
                int col = cb + nj * 8 + 2 * t;
                float ba = __ldg(&b1[col]), bb = __ldg(&b1[col + 1]);
                __half2 h0 = __floats2half2_rn(fmaxf(acc[mi][nj][0] + ba, 0.f),
                                               fmaxf(acc[mi][nj][1] + bb, 0.f));
                __half2 h1 = __floats2half2_rn(fmaxf(acc[mi][nj][2] + ba, 0.f),
                                               fmaxf(acc[mi][nj][3] + bb, 0.f));
                int r = wm + mi * 16 + g;
                *(__half2*)(smx + H_OFF + r * H_STRIDE + col * 2)       = h0;
                *(__half2*)(smx + H_OFF + (r + 8) * H_STRIDE + col * 2) = h1;
            }
        }
    }
    __syncthreads();

    // ---- root phase: layer2 acc += h @ root2 (4 chunks of K=64) ----
    for (int c = 0; c < 4; c++) {
        int s = c & 1;
        CP_WAIT(0);
        __syncthreads();
        if (c + 1 < 4) { ldRootB(c + 1, s ^ 1); CP_COMMIT(); }
        if (L == 1) {
            const char* Bb = smx + B_OFF + s * B_STAGE;
#pragma unroll
            for (int ks = 0; ks < 4; ks++) {
                int kb = ks * 16;
                uint32_t a[2][4];
#pragma unroll
                for (int mi = 0; mi < 2; mi++) {
                    const char* ar = smx + H_OFF + (wm + mi * 16 + g) * H_STRIDE
                                     + (c * 64 + kb) * 2 + t * 4;
                    a[mi][0] = *(const uint32_t*)ar;
                    a[mi][1] = *(const uint32_t*)(ar + 8 * H_STRIDE);
                    a[mi][2] = *(const uint32_t*)(ar + 16);
                    a[mi][3] = *(const uint32_t*)(ar + 8 * H_STRIDE + 16);
                }
#pragma unroll
                for (int nj = 0; nj < 8; nj++) {
                    int n = cb + nj * 8 + g;
                    const char* br = Bb + n * 144 + kb * 2 + t * 4;
                    uint32_t b0  = *(const uint32_t*)br;
                    uint32_t b1v = *(const uint32_t*)(br + 16);
                    mma_f16(acc[0][nj], a[0], b0, b1v);
                    mma_f16(acc[1][nj], a[1], b0, b1v);
                }
            }
        }
        __syncthreads();
    }

    // ---- layer2 final store ----
    if (L == 1) {
#pragma unroll
        for (int mi = 0; mi < 2; mi++) {
            int r0g = row0 + wm + mi * 16 + g;
#pragma unroll
            for (int nj = 0; nj < 8; nj++) {
                int col = cb + nj * 8 + 2 * t;
                float ba = __ldg(&b2[col]), bb = __ldg(&b2[col + 1]);
                if (r0g < ND)
                    *(float2*)(out + (size_t)r0g * D + col) =
                        make_float2(acc[mi][nj][0] + ba, acc[mi][nj][1] + bb);
                if (r0g + 8 < ND)
                    *(float2*)(out + (size_t)(r0g + 8) * D + col) =
                        make_float2(acc[mi][nj][2] + ba, acc[mi][nj][3] + bb);
            }
        }
    }
}

// ---------------------------------------------------------------------------
extern "C" void kernel_launch(void* const* d_in, const int* in_sizes, int n_in,
                              void* d_out, int out_size) {
    const float* x_src = (const float*)d_in[0];
    const float* x_dst = (const float*)d_in[1];
    const void*  ei    = d_in[2];
    const void*  et    = d_in[3];
    const float* w1    = (const float*)d_in[4];
    const float* root1 = (const float*)d_in[5];
    const float* b1    = (const float*)d_in[6];
    const float* w2    = (const float*)d_in[7];
    const float* root2 = (const float*)d_in[8];
    const float* b2    = (const float*)d_in[9];
    float* out = (float*)d_out;
    int E = in_sizes[3];

    cudaFuncSetAttribute(fused_all, cudaFuncAttributeMaxDynamicSharedMemorySize, SMEM_T);

    prep_kernel<<<(2 * NC * 256 * 4 + 255) / 256, 256>>>(w1, root1, w2, root2);
    zero_kernel<<<2368, 256>>>();
    scatter_kernel<<<(E + 7) / 8, 256>>>(x_src, ei, et, E);

    fused_all<<<GRID_M, THREADS, SMEM_T>>>(x_dst, b1, b2, out);
}